// round 13
// baseline (speedup 1.0000x reference)
#include <cuda_runtime.h>
#include <cuda_bf16.h>
#include <math.h>
#include <cstdint>

// Problem constants
#define BB   4
#define LL   2048
#define LF   1025
#define PP   512
#define CC   8
#define PCN  4096
#define NBL  8
#define BSZ  64
#define KPAD 1032
#define PHY(k) ((k) ^ (((k) >> 4) & 15))
#define XSTR 70            // paired operand plane row stride (words)

// named barrier over 64 threads (2 warps); ids 1..15, 0 reserved for __syncthreads
#define BAR64(id) asm volatile("bar.sync %0, 64;" :: "r"(id) : "memory")

typedef unsigned long long u64;

// 67.6 MB frequency scratch: [b][pc][k] bf16x2 (re low, im high)
__device__ uint32_t g_Y[(size_t)BB * PCN * KPAD];
// paired weight images: [layer][n][nr=128][np=64] bf16x2
__device__ uint32_t g_Wimg[2 * 8 * 8192];
// twiddle tables
__device__ float2 g_W1024[1024];
__device__ float2 g_Whalf[1025];

extern __shared__ unsigned char smbase[];

// ---------- helpers ----------
__device__ __forceinline__ float gelu_fast(float v) {
    float u = 0.7978845608028654f * v * (1.0f + 0.044715f * v * v);
    float th; asm("tanh.approx.f32 %0, %1;" : "=f"(th) : "f"(u));
    return 0.5f * v * (1.0f + th);
}
__device__ __forceinline__ float2 cmulf(float2 x, float2 w) {
    return make_float2(x.x * w.x - x.y * w.y, x.x * w.y + x.y * w.x);
}
__device__ __forceinline__ float2 ldwt(const float2* W, int e, bool inv) {
    float2 w = W[e]; if (inv) w.y = -w.y; return w;
}
__device__ __forceinline__ void bfly4(float2& a, float2& b, float2& c, float2& d,
                                      float2 w1, float2 w2, float2 w3, bool inv) {
    float2 B = cmulf(b, w1), C = cmulf(c, w2), D = cmulf(d, w3);
    float2 t0 = make_float2(a.x + C.x, a.y + C.y);
    float2 t1 = make_float2(a.x - C.x, a.y - C.y);
    float2 t2 = make_float2(B.x + D.x, B.y + D.y);
    float2 t3 = make_float2(B.x - D.x, B.y - D.y);
    a = make_float2(t0.x + t2.x, t0.y + t2.y);
    c = make_float2(t0.x - t2.x, t0.y - t2.y);
    if (!inv) { b = make_float2(t1.x + t3.y, t1.y - t3.x);
                d = make_float2(t1.x - t3.y, t1.y + t3.x); }
    else      { b = make_float2(t1.x - t3.y, t1.y + t3.x);
                d = make_float2(t1.x + t3.y, t1.y - t3.x); }
}
__device__ __forceinline__ void bfly4n(float2& a, float2& b, float2& c, float2& d, bool inv) {
    float2 t0 = make_float2(a.x + c.x, a.y + c.y);
    float2 t1 = make_float2(a.x - c.x, a.y - c.y);
    float2 t2 = make_float2(b.x + d.x, b.y + d.y);
    float2 t3 = make_float2(b.x - d.x, b.y - d.y);
    a = make_float2(t0.x + t2.x, t0.y + t2.y);
    c = make_float2(t0.x - t2.x, t0.y - t2.y);
    if (!inv) { b = make_float2(t1.x + t3.y, t1.y - t3.x);
                d = make_float2(t1.x - t3.y, t1.y + t3.x); }
    else      { b = make_float2(t1.x - t3.y, t1.y + t3.x);
                d = make_float2(t1.x + t3.y, t1.y - t3.x); }
}
__device__ __forceinline__ uint32_t pkbf(float a, float b) {
    __nv_bfloat162 h = __floats2bfloat162_rn(a, b);
    return *(uint32_t*)&h;
}
__device__ __forceinline__ float2 upbf(uint32_t w) {
    __nv_bfloat162 h = *(__nv_bfloat162*)&w;
    return __bfloat1622float2(h);
}
__device__ __forceinline__ void mma16816(float* d, uint32_t a0, uint32_t a1,
                                         uint32_t a2, uint32_t a3,
                                         uint32_t b0, uint32_t b1) {
    asm volatile("mma.sync.aligned.m16n8k16.row.col.f32.bf16.bf16.f32 "
                 "{%0,%1,%2,%3}, {%4,%5,%6,%7}, {%8,%9}, {%0,%1,%2,%3};"
                 : "+f"(d[0]), "+f"(d[1]), "+f"(d[2]), "+f"(d[3])
                 : "r"(a0), "r"(a1), "r"(a2), "r"(a3), "r"(b0), "r"(b1));
}
// paired position of operand word w (0..63)
__device__ __forceinline__ int npw(int w) {
    return ((w >> 3) << 3) + ((w & 3) << 1) + ((w >> 2) & 1);
}

// In-smem 1024-point FFT: 3 passes, PHY bank swizzle. t = 0..63.
// Syncs between passes are LINE-LOCAL (named barrier `barid`, 2 warps).
// NO trailing sync — caller adds the scope it needs after P3.
__device__ __forceinline__ void fft1024_f(float2* ls, const float2* W, int t, bool inv,
                                          int barid) {
    {
        const int i0 = t << 4;
        const int rt = ((t & 3) << 4) | (((t >> 2) & 3) << 2) | (t >> 4);
        float2 x[16];
        #pragma unroll
        for (int m = 0; m < 16; ++m)
            x[m] = ls[PHY(rt + ((m & 3) << 8) + ((m >> 2) << 6))];
        #pragma unroll
        for (int a = 0; a < 4; ++a)
            bfly4n(x[4 * a], x[4 * a + 1], x[4 * a + 2], x[4 * a + 3], inv);
        #pragma unroll
        for (int r = 1; r < 4; ++r) {
            int e2 = r << 6;
            bfly4(x[r], x[4 + r], x[8 + r], x[12 + r],
                  ldwt(W, e2, inv), ldwt(W, 2 * e2, inv), ldwt(W, 3 * e2, inv), inv);
        }
        bfly4n(x[0], x[4], x[8], x[12], inv);
        #pragma unroll
        for (int m = 0; m < 16; ++m) ls[PHY(i0 + m)] = x[m];
    }
    BAR64(barid);
    {
        const int j = t & 15;
        const int i0 = ((t >> 4) << 8) + j;
        float2 x[16];
        #pragma unroll
        for (int m = 0; m < 16; ++m) x[m] = ls[PHY(i0 + (m << 4))];
        const int e1 = j << 4;
        {
            float2 w1 = ldwt(W, e1, inv), w2 = ldwt(W, 2 * e1, inv), w3 = ldwt(W, 3 * e1, inv);
            #pragma unroll
            for (int a = 0; a < 4; ++a)
                bfly4(x[4 * a], x[4 * a + 1], x[4 * a + 2], x[4 * a + 3], w1, w2, w3, inv);
        }
        #pragma unroll
        for (int r = 0; r < 4; ++r) {
            int e2 = (j << 2) + (r << 6);
            bfly4(x[r], x[4 + r], x[8 + r], x[12 + r],
                  ldwt(W, e2, inv), ldwt(W, 2 * e2, inv), ldwt(W, 3 * e2, inv), inv);
        }
        #pragma unroll
        for (int m = 0; m < 16; ++m) ls[PHY(i0 + (m << 4))] = x[m];
    }
    BAR64(barid);
    #pragma unroll
    for (int it = 0; it < 4; ++it) {
        int j = t + (it << 6);
        float2 w1 = ldwt(W, j, inv), w2 = ldwt(W, 2 * j, inv), w3 = ldwt(W, 3 * j, inv);
        float2 a = ls[PHY(j)], b = ls[PHY(j + 256)], c = ls[PHY(j + 512)], d = ls[PHY(j + 768)];
        bfly4(a, b, c, d, w1, w2, w3, inv);
        ls[PHY(j)] = a; ls[PHY(j + 256)] = b; ls[PHY(j + 512)] = c; ls[PHY(j + 768)] = d;
    }
}

// ---------- K_tw ----------
__global__ void k_tw() {
    for (int j = threadIdx.x; j < 1024; j += 256) {
        float sv, cv; sincospif((float)j * (1.0f / 512.0f), &sv, &cv);
        g_W1024[j] = make_float2(cv, -sv);
    }
    for (int k = threadIdx.x; k <= 1024; k += 256) {
        float sv, cv; sincospif((float)k * (1.0f / 1024.0f), &sv, &cv);
        g_Whalf[k] = make_float2(cv, sv);
    }
}

// ---------- K0: pack weight images (paired layout) ----------
__global__ void k_wprep(const float* __restrict__ w1g, const float* __restrict__ w2g) {
    const int n = blockIdx.x, l = blockIdx.y;
    const float* wg = l ? w2g : w1g;
    uint32_t* dst = g_Wimg + (size_t)(l * 8 + n) * 8192;
    for (int idx = threadIdx.x; idx < 8192; idx += 256) {
        int o = idx >> 6, w = idx & 63;
        float v[2];
        #pragma unroll
        for (int q = 0; q < 2; ++q) {
            int kk = 2 * w + q;
            if (o < 64)
                v[q] = (kk < 64) ? wg[n * 4096 + kk * 64 + o]
                                 : -wg[32768 + n * 4096 + (kk - 64) * 64 + o];
            else
                v[q] = (kk < 64) ? wg[32768 + n * 4096 + kk * 64 + (o - 64)]
                                 : wg[n * 4096 + (kk - 64) * 64 + (o - 64)];
        }
        dst[o * 64 + npw(w)] = pkbf(v[0], v[1]);
    }
}

// ---------- K1: forward rfft ----------
__global__ __launch_bounds__(256, 3) void k_fwd(const float* __restrict__ x) {
    float2* sm = (float2*)smbase;
    float2* W = sm;
    float2* lines = sm + 1024;
    const int tid = threadIdx.x;
    const int u = tid >> 6, t = tid & 63;
    const int pc0 = blockIdx.x * 4;
    const int b = blockIdx.y;

    for (int j = tid; j < 1024; j += 256) W[j] = g_W1024[j];
    {
        const float* xb = x + (size_t)b * LL * PCN + pc0;
        for (int l = tid; l < 2048; l += 256) {
            float4 v = *(const float4*)(xb + (size_t)l * PCN);
            int fo = 2 * PHY(l >> 1) + (l & 1);
            float* s0 = (float*)lines;
            s0[0 * 2050 + fo] = v.x;
            s0[1 * 2050 + fo] = v.y;
            s0[2 * 2050 + fo] = v.z;
            s0[3 * 2050 + fo] = v.w;
        }
    }
    __syncthreads();

    float2* ls = lines + u * 1025;
    fft1024_f(ls, W, t, false, 1 + u);
    BAR64(1 + u);   // line-local: unpack reads only this line

    {
        uint32_t* out = g_Y + ((size_t)(b * PCN + pc0 + u)) * KPAD;
        const float SC = 0.02209708691207961f;
        for (int k = t; k <= 1024; k += 64) {
            float2 Zk = ls[PHY(k & 1023)];
            float2 Zm = ls[PHY((1024 - k) & 1023)];
            float er = 0.5f * (Zk.x + Zm.x), ei = 0.5f * (Zk.y - Zm.y);
            float orr = 0.5f * (Zk.y + Zm.y), oi = 0.5f * (Zm.x - Zk.x);
            float2 wv = g_Whalf[k];
            out[k] = pkbf(SC * (er + wv.x * orr + wv.y * oi),
                          SC * (ei + wv.x * oi - wv.y * orr));
        }
    }
}

// ---------- K2: block MLP, M=32 per warp, pair-scoped barriers ----------
__global__ __launch_bounds__(256, 2) void k_mlp(const float* __restrict__ b1g,
                                                const float* __restrict__ b2g) {
    uint32_t* Xa  = (uint32_t*)smbase;
    uint32_t* W1s = Xa + 128 * XSTR;
    uint32_t* W2s = W1s + 128 * XSTR;
    float* bias1 = (float*)(W2s + 128 * XSTR);
    float* bias2 = bias1 + 128;
    uint16_t* Oa = (uint16_t*)Xa;                 // [128][XSTR] bf16 bits (real)
    uint16_t* Ob = Oa + 128 * XSTR;               // (imag)

    const int tid = threadIdx.x;
    const int w = tid >> 5, l = tid & 31;
    const int g = l >> 2, c = l & 3;
    const int wq = w & 3, wh = w >> 2;            // m-group / N-half
    const int k0 = blockIdx.x * 128;
    const int n = blockIdx.y >> 3, cch = blockIdx.y & 7;
    const int b = blockIdx.z;
    const int pbar = 1 + wq;                      // pair barrier {wq, wq+4}

    {   // weights -> smem, restride 64 -> XSTR
        const uint32_t* s1 = g_Wimg + (size_t)n * 8192;
        const uint32_t* s2 = g_Wimg + (size_t)(8 + n) * 8192;
        for (int idx = tid; idx < 8192; idx += 256) {
            int r = idx >> 6, col = idx & 63;
            W1s[r * XSTR + col] = s1[idx];
            W2s[r * XSTR + col] = s2[idx];
        }
    }
    if (tid < 128) {
        bias1[tid] = (tid < 64) ? b1g[n * 64 + tid] : b1g[512 + n * 64 + (tid - 64)];
        bias2[tid] = (tid < 64) ? b2g[n * 64 + tid] : b2g[512 + n * 64 + (tid - 64)];
    }
    const size_t jstride = (size_t)8 * KPAD;
    const size_t rbase = ((size_t)b * PCN + (size_t)(n * 64) * 8 + cch) * KPAD + k0;
    {   // X fill: PRMT repack of bf16 pairs into paired A-layout
        const int m = tid & 127, ih = tid >> 7;
        const bool valid = (k0 + m <= 1024);
        const uint32_t* src = g_Y + rbase + m;
        for (int j = 2 * ih; j < 64; j += 4) {
            uint32_t w0 = 0, w1 = 0;
            if (valid) { w0 = src[(size_t)j * jstride]; w1 = src[(size_t)(j + 1) * jstride]; }
            uint32_t rp, ip;
            asm("prmt.b32 %0, %1, %2, 0x5410;" : "=r"(rp) : "r"(w0), "r"(w1));
            asm("prmt.b32 %0, %1, %2, 0x7632;" : "=r"(ip) : "r"(w0), "r"(w1));
            Xa[m * XSTR + npw(j >> 1)]        = rp;
            Xa[m * XSTR + npw(32 + (j >> 1))] = ip;
        }
    }
    __syncthreads();

    const int r0 = wq * 32 + g;
    const int co = 2 * c;

    // ---- layer 1
    float a0c[8][4], a1c[8][4];
    #pragma unroll
    for (int t = 0; t < 8; ++t) {
        a0c[t][0] = a0c[t][1] = a0c[t][2] = a0c[t][3] = 0.f;
        a1c[t][0] = a1c[t][1] = a1c[t][2] = a1c[t][3] = 0.f;
    }
    #pragma unroll
    for (int s = 0; s < 8; ++s) {
        const int cs = 8 * s + co;
        uint2 aa0 = *(const uint2*)(Xa + r0 * XSTR + cs);
        uint2 ab0 = *(const uint2*)(Xa + (r0 + 8) * XSTR + cs);
        uint2 aa1 = *(const uint2*)(Xa + (r0 + 16) * XSTR + cs);
        uint2 ab1 = *(const uint2*)(Xa + (r0 + 24) * XSTR + cs);
        #pragma unroll
        for (int t = 0; t < 8; ++t) {
            const int nr = (wh * 8 + t) * 8 + g;
            uint2 bw = *(const uint2*)(W1s + nr * XSTR + cs);
            mma16816(a0c[t], aa0.x, ab0.x, aa0.y, ab0.y, bw.x, bw.y);
            mma16816(a1c[t], aa1.x, ab1.x, aa1.y, ab1.y, bw.x, bw.y);
        }
    }
    uint32_t h00[8], h01[8], h10[8], h11[8];
    #pragma unroll
    for (int t = 0; t < 8; ++t) {
        float2 bv = *(float2*)(bias1 + (wh * 8 + t) * 8 + co);
        h00[t] = pkbf(gelu_fast(a0c[t][0] + bv.x), gelu_fast(a0c[t][1] + bv.y));
        h01[t] = pkbf(gelu_fast(a0c[t][2] + bv.x), gelu_fast(a0c[t][3] + bv.y));
        h10[t] = pkbf(gelu_fast(a1c[t][0] + bv.x), gelu_fast(a1c[t][1] + bv.y));
        h11[t] = pkbf(gelu_fast(a1c[t][2] + bv.x), gelu_fast(a1c[t][3] + bv.y));
    }
    BAR64(pbar);   // pair {wq, wq+4} done reading Xa band -> H overlay safe
    #pragma unroll
    for (int t = 0; t < 8; ++t) {
        const int np = npw(wh * 32 + t * 4 + c);
        Xa[r0 * XSTR + np]        = h00[t];
        Xa[(r0 + 8) * XSTR + np]  = h01[t];
        Xa[(r0 + 16) * XSTR + np] = h10[t];
        Xa[(r0 + 24) * XSTR + np] = h11[t];
    }
    BAR64(pbar);   // pair's H band complete

    // ---- layer 2
    #pragma unroll
    for (int t = 0; t < 8; ++t) {
        a0c[t][0] = a0c[t][1] = a0c[t][2] = a0c[t][3] = 0.f;
        a1c[t][0] = a1c[t][1] = a1c[t][2] = a1c[t][3] = 0.f;
    }
    #pragma unroll
    for (int s = 0; s < 8; ++s) {
        const int cs = 8 * s + co;
        uint2 aa0 = *(const uint2*)(Xa + r0 * XSTR + cs);
        uint2 ab0 = *(const uint2*)(Xa + (r0 + 8) * XSTR + cs);
        uint2 aa1 = *(const uint2*)(Xa + (r0 + 16) * XSTR + cs);
        uint2 ab1 = *(const uint2*)(Xa + (r0 + 24) * XSTR + cs);
        #pragma unroll
        for (int t = 0; t < 8; ++t) {
            const int nr = (wh * 8 + t) * 8 + g;
            uint2 bw = *(const uint2*)(W2s + nr * XSTR + cs);
            mma16816(a0c[t], aa0.x, ab0.x, aa0.y, ab0.y, bw.x, bw.y);
            mma16816(a1c[t], aa1.x, ab1.x, aa1.y, ab1.y, bw.x, bw.y);
        }
    }
    BAR64(pbar);   // pair done reading H band -> O overlay safe

    {   // epilogue 2: bias + bf16 stores into Oa/Ob
        uint16_t* O = wh ? Ob : Oa;
        const float* bs = bias2 + wh * 64;
        #pragma unroll
        for (int t = 0; t < 8; ++t) {
            const int j = t * 8 + co;
            float2 bv = make_float2(bs[j], bs[j + 1]);
            __nv_bfloat16 v0 = __float2bfloat16(a0c[t][0] + bv.x);
            __nv_bfloat16 v1 = __float2bfloat16(a0c[t][1] + bv.y);
            __nv_bfloat16 v2 = __float2bfloat16(a0c[t][2] + bv.x);
            __nv_bfloat16 v3 = __float2bfloat16(a0c[t][3] + bv.y);
            __nv_bfloat16 v4 = __float2bfloat16(a1c[t][0] + bv.x);
            __nv_bfloat16 v5 = __float2bfloat16(a1c[t][1] + bv.y);
            __nv_bfloat16 v6 = __float2bfloat16(a1c[t][2] + bv.x);
            __nv_bfloat16 v7 = __float2bfloat16(a1c[t][3] + bv.y);
            O[r0 * XSTR + j]            = *(uint16_t*)&v0;
            O[r0 * XSTR + j + 1]        = *(uint16_t*)&v1;
            O[(r0 + 8) * XSTR + j]      = *(uint16_t*)&v2;
            O[(r0 + 8) * XSTR + j + 1]  = *(uint16_t*)&v3;
            O[(r0 + 16) * XSTR + j]     = *(uint16_t*)&v4;
            O[(r0 + 16) * XSTR + j + 1] = *(uint16_t*)&v5;
            O[(r0 + 24) * XSTR + j]     = *(uint16_t*)&v6;
            O[(r0 + 24) * XSTR + j + 1] = *(uint16_t*)&v7;
        }
    }
    __syncthreads();   // final store reads all bands

    {   // coalesced bf16x2 store
        const int m = tid & 127, jh = tid >> 7;
        if (k0 + m <= 1024) {
            uint32_t* dst = g_Y + rbase + m;
            for (int j = jh; j < 64; j += 2)
                dst[(size_t)j * jstride] =
                    (uint32_t)Oa[m * XSTR + j] | ((uint32_t)Ob[m * XSTR + j] << 16);
        }
    }
}

// ---------- K3: inverse rfft + residual (pack fused into load) ----------
__global__ __launch_bounds__(256, 3) void k_inv(const float* __restrict__ x,
                                                float* __restrict__ out) {
    float2* sm = (float2*)smbase;
    float2* W = sm;
    float2* lines = sm + 1024;
    const int tid = threadIdx.x;
    const int u = tid >> 6, t = tid & 63;
    const int pc0 = blockIdx.x * 4;
    const int b = blockIdx.y;

    for (int j = tid; j < 1024; j += 256) W[j] = g_W1024[j];
    float2* ls = lines + u * 1026;
    {
        const uint32_t* src = g_Y + ((size_t)(b * PCN + pc0 + u)) * KPAD;
        const float SCI = 0.04419417382415922f;
        for (int k = t; k <= 512; k += 64) {
            float2 Xk = upbf(src[k]);
            float2 Xj = upbf(src[1024 - k]);
            if (k == 0) { Xk.y = 0.f; Xj.y = 0.f; }
            float ex = 0.5f * (Xk.x + Xj.x), ey = 0.5f * (Xk.y - Xj.y);
            float dx = 0.5f * (Xk.x - Xj.x), dy = 0.5f * (Xk.y + Xj.y);
            float2 wv = g_Whalf[k];
            float ox = wv.x * dx - wv.y * dy;
            float oy = wv.x * dy + wv.y * dx;
            ls[PHY(k)] = make_float2(SCI * (ex - oy), SCI * (ey + ox));
            if (k > 0 && k < 512)
                ls[PHY(1024 - k)] = make_float2(SCI * (ex + oy), SCI * (ox - ey));
        }
    }
    __syncthreads();

    fft1024_f(ls, W, t, true, 1 + u);
    __syncthreads();   // residual phase reads across all lines

    {
        const float* s0 = (const float*)lines;
        const float* xb = x + (size_t)b * LL * PCN + pc0;
        float* ob = out + (size_t)b * LL * PCN + pc0;
        for (int l = tid; l < 2048; l += 256) {
            float4 xv = *(const float4*)(xb + (size_t)l * PCN);
            int fo = 2 * PHY(l >> 1) + (l & 1);
            float4 r;
            r.x = xv.x + s0[0 * 2052 + fo];
            r.y = xv.y + s0[1 * 2052 + fo];
            r.z = xv.z + s0[2 * 2052 + fo];
            r.w = xv.w + s0[3 * 2052 + fo];
            *(float4*)(ob + (size_t)l * PCN) = r;
        }
    }
}

extern "C" void kernel_launch(void* const* d_in, const int* in_sizes, int n_in,
                              void* d_out, int out_size) {
    const float* x  = (const float*)d_in[0];
    const float* w1 = (const float*)d_in[1];
    const float* b1 = (const float*)d_in[2];
    const float* w2 = (const float*)d_in[3];
    const float* b2 = (const float*)d_in[4];
    float* out = (float*)d_out;

    const size_t s1 = (size_t)(1024 + 4 * 1025) * sizeof(float2);   // 40,992 B
    const size_t s2 = (size_t)3 * 128 * XSTR * 4 + 1024;            // 108,544 B
    const size_t s3 = (size_t)(1024 + 4 * 1026) * sizeof(float2);   // 41,024 B

    cudaFuncSetAttribute(k_fwd, cudaFuncAttributeMaxDynamicSharedMemorySize, (int)s1);
    cudaFuncSetAttribute(k_mlp, cudaFuncAttributeMaxDynamicSharedMemorySize, (int)s2);
    cudaFuncSetAttribute(k_inv, cudaFuncAttributeMaxDynamicSharedMemorySize, (int)s3);

    k_tw<<<1, 256>>>();
    k_wprep<<<dim3(8, 2), 256>>>(w1, w2);
    k_fwd<<<dim3(PCN / 4, BB), 256, s1>>>(x);
    k_mlp<<<dim3(9, 64, BB), 256, s2>>>(b1, b2);
    k_inv<<<dim3(PCN / 4, BB), 256, s3>>>(x, out);
}

// round 14
// speedup vs baseline: 1.0153x; 1.0153x over previous
#include <cuda_runtime.h>
#include <cuda_bf16.h>
#include <math.h>
#include <cstdint>

// Problem constants
#define BB   4
#define LL   2048
#define LF   1025
#define PP   512
#define CC   8
#define PCN  4096
#define NBL  8
#define BSZ  64
#define KPAD 1032
#define PHY(k) ((k) ^ (((k) >> 4) & 15))
#define XSTR 70            // paired operand plane row stride (words)

typedef unsigned long long u64;

// 67.6 MB frequency scratch: [b][pc][k] bf16x2 (re low, im high)
__device__ uint32_t g_Y[(size_t)BB * PCN * KPAD];
// paired weight images: [layer][n][nr=128][np=64] bf16x2
__device__ uint32_t g_Wimg[2 * 8 * 8192];
// twiddle tables
__device__ float2 g_W1024[1024];
__device__ float2 g_Whalf[1025];

extern __shared__ unsigned char smbase[];

// ---------- helpers ----------
__device__ __forceinline__ float gelu_fast(float v) {
    float u = 0.7978845608028654f * v * (1.0f + 0.044715f * v * v);
    float th; asm("tanh.approx.f32 %0, %1;" : "=f"(th) : "f"(u));
    return 0.5f * v * (1.0f + th);
}
__device__ __forceinline__ float2 cmulf(float2 x, float2 w) {
    return make_float2(x.x * w.x - x.y * w.y, x.x * w.y + x.y * w.x);
}
__device__ __forceinline__ float2 ldwt(const float2* W, int e, bool inv) {
    float2 w = W[e]; if (inv) w.y = -w.y; return w;
}
__device__ __forceinline__ void bfly4(float2& a, float2& b, float2& c, float2& d,
                                      float2 w1, float2 w2, float2 w3, bool inv) {
    float2 B = cmulf(b, w1), C = cmulf(c, w2), D = cmulf(d, w3);
    float2 t0 = make_float2(a.x + C.x, a.y + C.y);
    float2 t1 = make_float2(a.x - C.x, a.y - C.y);
    float2 t2 = make_float2(B.x + D.x, B.y + D.y);
    float2 t3 = make_float2(B.x - D.x, B.y - D.y);
    a = make_float2(t0.x + t2.x, t0.y + t2.y);
    c = make_float2(t0.x - t2.x, t0.y - t2.y);
    if (!inv) { b = make_float2(t1.x + t3.y, t1.y - t3.x);
                d = make_float2(t1.x - t3.y, t1.y + t3.x); }
    else      { b = make_float2(t1.x - t3.y, t1.y + t3.x);
                d = make_float2(t1.x + t3.y, t1.y - t3.x); }
}
__device__ __forceinline__ void bfly4n(float2& a, float2& b, float2& c, float2& d, bool inv) {
    float2 t0 = make_float2(a.x + c.x, a.y + c.y);
    float2 t1 = make_float2(a.x - c.x, a.y - c.y);
    float2 t2 = make_float2(b.x + d.x, b.y + d.y);
    float2 t3 = make_float2(b.x - d.x, b.y - d.y);
    a = make_float2(t0.x + t2.x, t0.y + t2.y);
    c = make_float2(t0.x - t2.x, t0.y - t2.y);
    if (!inv) { b = make_float2(t1.x + t3.y, t1.y - t3.x);
                d = make_float2(t1.x - t3.y, t1.y + t3.x); }
    else      { b = make_float2(t1.x - t3.y, t1.y + t3.x);
                d = make_float2(t1.x + t3.y, t1.y - t3.x); }
}
__device__ __forceinline__ uint32_t pkbf(float a, float b) {
    __nv_bfloat162 h = __floats2bfloat162_rn(a, b);
    return *(uint32_t*)&h;
}
__device__ __forceinline__ float2 upbf(uint32_t w) {
    __nv_bfloat162 h = *(__nv_bfloat162*)&w;
    return __bfloat1622float2(h);
}
__device__ __forceinline__ void mma16816(float* d, uint32_t a0, uint32_t a1,
                                         uint32_t a2, uint32_t a3,
                                         uint32_t b0, uint32_t b1) {
    asm volatile("mma.sync.aligned.m16n8k16.row.col.f32.bf16.bf16.f32 "
                 "{%0,%1,%2,%3}, {%4,%5,%6,%7}, {%8,%9}, {%0,%1,%2,%3};"
                 : "+f"(d[0]), "+f"(d[1]), "+f"(d[2]), "+f"(d[3])
                 : "r"(a0), "r"(a1), "r"(a2), "r"(a3), "r"(b0), "r"(b1));
}
// paired position of operand word w (0..63)
__device__ __forceinline__ int npw(int w) {
    return ((w >> 3) << 3) + ((w & 3) << 1) + ((w >> 2) & 1);
}

// In-smem 1024-point FFT: 3 passes, PHY bank swizzle. t = 0..63.
__device__ __forceinline__ void fft1024_f(float2* ls, const float2* W, int t, bool inv) {
    {
        const int i0 = t << 4;
        const int rt = ((t & 3) << 4) | (((t >> 2) & 3) << 2) | (t >> 4);
        float2 x[16];
        #pragma unroll
        for (int m = 0; m < 16; ++m)
            x[m] = ls[PHY(rt + ((m & 3) << 8) + ((m >> 2) << 6))];
        #pragma unroll
        for (int a = 0; a < 4; ++a)
            bfly4n(x[4 * a], x[4 * a + 1], x[4 * a + 2], x[4 * a + 3], inv);
        #pragma unroll
        for (int r = 1; r < 4; ++r) {
            int e2 = r << 6;
            bfly4(x[r], x[4 + r], x[8 + r], x[12 + r],
                  ldwt(W, e2, inv), ldwt(W, 2 * e2, inv), ldwt(W, 3 * e2, inv), inv);
        }
        bfly4n(x[0], x[4], x[8], x[12], inv);
        #pragma unroll
        for (int m = 0; m < 16; ++m) ls[PHY(i0 + m)] = x[m];
    }
    __syncthreads();
    {
        const int j = t & 15;
        const int i0 = ((t >> 4) << 8) + j;
        float2 x[16];
        #pragma unroll
        for (int m = 0; m < 16; ++m) x[m] = ls[PHY(i0 + (m << 4))];
        const int e1 = j << 4;
        {
            float2 w1 = ldwt(W, e1, inv), w2 = ldwt(W, 2 * e1, inv), w3 = ldwt(W, 3 * e1, inv);
            #pragma unroll
            for (int a = 0; a < 4; ++a)
                bfly4(x[4 * a], x[4 * a + 1], x[4 * a + 2], x[4 * a + 3], w1, w2, w3, inv);
        }
        #pragma unroll
        for (int r = 0; r < 4; ++r) {
            int e2 = (j << 2) + (r << 6);
            bfly4(x[r], x[4 + r], x[8 + r], x[12 + r],
                  ldwt(W, e2, inv), ldwt(W, 2 * e2, inv), ldwt(W, 3 * e2, inv), inv);
        }
        #pragma unroll
        for (int m = 0; m < 16; ++m) ls[PHY(i0 + (m << 4))] = x[m];
    }
    __syncthreads();
    #pragma unroll
    for (int it = 0; it < 4; ++it) {
        int j = t + (it << 6);
        float2 w1 = ldwt(W, j, inv), w2 = ldwt(W, 2 * j, inv), w3 = ldwt(W, 3 * j, inv);
        float2 a = ls[PHY(j)], b = ls[PHY(j + 256)], c = ls[PHY(j + 512)], d = ls[PHY(j + 768)];
        bfly4(a, b, c, d, w1, w2, w3, inv);
        ls[PHY(j)] = a; ls[PHY(j + 256)] = b; ls[PHY(j + 512)] = c; ls[PHY(j + 768)] = d;
    }
    __syncthreads();
}

// ---------- K_tw ----------
__global__ void k_tw() {
    for (int j = threadIdx.x; j < 1024; j += 256) {
        float sv, cv; sincospif((float)j * (1.0f / 512.0f), &sv, &cv);
        g_W1024[j] = make_float2(cv, -sv);
    }
    for (int k = threadIdx.x; k <= 1024; k += 256) {
        float sv, cv; sincospif((float)k * (1.0f / 1024.0f), &sv, &cv);
        g_Whalf[k] = make_float2(cv, sv);
    }
}

// ---------- K0: pack weight images (paired layout) ----------
__global__ void k_wprep(const float* __restrict__ w1g, const float* __restrict__ w2g) {
    const int n = blockIdx.x, l = blockIdx.y;
    const float* wg = l ? w2g : w1g;
    uint32_t* dst = g_Wimg + (size_t)(l * 8 + n) * 8192;
    for (int idx = threadIdx.x; idx < 8192; idx += 256) {
        int o = idx >> 6, w = idx & 63;
        float v[2];
        #pragma unroll
        for (int q = 0; q < 2; ++q) {
            int kk = 2 * w + q;
            if (o < 64)
                v[q] = (kk < 64) ? wg[n * 4096 + kk * 64 + o]
                                 : -wg[32768 + n * 4096 + (kk - 64) * 64 + o];
            else
                v[q] = (kk < 64) ? wg[32768 + n * 4096 + kk * 64 + (o - 64)]
                                 : wg[n * 4096 + (kk - 64) * 64 + (o - 64)];
        }
        dst[o * 64 + npw(w)] = pkbf(v[0], v[1]);
    }
}

// ---------- K1: forward rfft ----------
__global__ __launch_bounds__(256, 3) void k_fwd(const float* __restrict__ x) {
    float2* sm = (float2*)smbase;
    float2* W = sm;
    float2* lines = sm + 1024;
    const int tid = threadIdx.x;
    const int u = tid >> 6, t = tid & 63;
    const int pc0 = blockIdx.x * 4;
    const int b = blockIdx.y;

    for (int j = tid; j < 1024; j += 256) W[j] = g_W1024[j];
    {
        const float* xb = x + (size_t)b * LL * PCN + pc0;
        for (int l = tid; l < 2048; l += 256) {
            float4 v = *(const float4*)(xb + (size_t)l * PCN);
            int fo = 2 * PHY(l >> 1) + (l & 1);
            float* s0 = (float*)lines;
            s0[0 * 2050 + fo] = v.x;
            s0[1 * 2050 + fo] = v.y;
            s0[2 * 2050 + fo] = v.z;
            s0[3 * 2050 + fo] = v.w;
        }
    }
    __syncthreads();

    float2* ls = lines + u * 1025;
    fft1024_f(ls, W, t, false);

    {
        uint32_t* out = g_Y + ((size_t)(b * PCN + pc0 + u)) * KPAD;
        const float SC = 0.02209708691207961f;
        for (int k = t; k <= 1024; k += 64) {
            float2 Zk = ls[PHY(k & 1023)];
            float2 Zm = ls[PHY((1024 - k) & 1023)];
            float er = 0.5f * (Zk.x + Zm.x), ei = 0.5f * (Zk.y - Zm.y);
            float orr = 0.5f * (Zk.y + Zm.y), oi = 0.5f * (Zm.x - Zk.x);
            float2 wv = g_Whalf[k];
            out[k] = pkbf(SC * (er + wv.x * orr + wv.y * oi),
                          SC * (ei + wv.x * oi - wv.y * orr));
        }
    }
}

// ---------- K_nyq: MLP for the Nyquist column (k=1024) ----------
// grid (8 n, 8 c, 4 b), 128 threads; f32 GEMV pair on paired weight images.
__global__ void k_nyq(const float* __restrict__ b1g, const float* __restrict__ b2g) {
    __shared__ float xs[128];
    __shared__ float hs[128];
    __shared__ float os[128];
    const int n = blockIdx.x, cch = blockIdx.y, b = blockIdx.z;
    const int o = threadIdx.x;
    {
        int i = o & 63;
        float2 v = upbf(g_Y[((size_t)b * PCN + (size_t)n * 512 + i * 8 + cch) * KPAD + 1024]);
        xs[o] = (o < 64) ? v.x : v.y;
    }
    __syncthreads();
    {
        float acc = (o < 64) ? b1g[n * 64 + o] : b1g[512 + n * 64 + (o - 64)];
        const uint32_t* Wr = g_Wimg + (size_t)n * 8192 + o * 64;
        for (int w = 0; w < 64; ++w) {
            float2 wv = upbf(Wr[npw(w)]);
            acc += xs[2 * w] * wv.x + xs[2 * w + 1] * wv.y;
        }
        hs[o] = gelu_fast(acc);
    }
    __syncthreads();
    {
        float acc = (o < 64) ? b2g[n * 64 + o] : b2g[512 + n * 64 + (o - 64)];
        const uint32_t* Wr = g_Wimg + (size_t)(8 + n) * 8192 + o * 64;
        for (int w = 0; w < 64; ++w) {
            float2 wv = upbf(Wr[npw(w)]);
            acc += hs[2 * w] * wv.x + hs[2 * w + 1] * wv.y;
        }
        os[o] = acc;
    }
    __syncthreads();
    if (o < 64)
        g_Y[((size_t)b * PCN + (size_t)n * 512 + o * 8 + cch) * KPAD + 1024] =
            pkbf(os[o], os[64 + o]);
}

// ---------- K2: block MLP, M=32 per warp, N split across warp halves ----------
// grid (8 ktiles of 128 covering k<1024, 64 = n*8+c, B). Nyquist handled by k_nyq.
__global__ __launch_bounds__(256, 2) void k_mlp(const float* __restrict__ b1g,
                                                const float* __restrict__ b2g) {
    uint32_t* Xa  = (uint32_t*)smbase;
    uint32_t* W1s = Xa + 128 * XSTR;
    uint32_t* W2s = W1s + 128 * XSTR;
    float* bias1 = (float*)(W2s + 128 * XSTR);
    float* bias2 = bias1 + 128;
    uint16_t* Oa = (uint16_t*)Xa;                 // [128][XSTR] bf16 bits (real)
    uint16_t* Ob = Oa + 128 * XSTR;               // (imag)

    const int tid = threadIdx.x;
    const int w = tid >> 5, l = tid & 31;
    const int g = l >> 2, c = l & 3;
    const int wq = w & 3, wh = w >> 2;            // m-group / N-half
    const int k0 = blockIdx.x * 128;
    const int n = blockIdx.y >> 3, cch = blockIdx.y & 7;
    const int b = blockIdx.z;

    {   // weights -> smem, restride 64 -> XSTR
        const uint32_t* s1 = g_Wimg + (size_t)n * 8192;
        const uint32_t* s2 = g_Wimg + (size_t)(8 + n) * 8192;
        for (int idx = tid; idx < 8192; idx += 256) {
            int r = idx >> 6, col = idx & 63;
            W1s[r * XSTR + col] = s1[idx];
            W2s[r * XSTR + col] = s2[idx];
        }
    }
    if (tid < 128) {
        bias1[tid] = (tid < 64) ? b1g[n * 64 + tid] : b1g[512 + n * 64 + (tid - 64)];
        bias2[tid] = (tid < 64) ? b2g[n * 64 + tid] : b2g[512 + n * 64 + (tid - 64)];
    }
    const size_t jstride = (size_t)8 * KPAD;
    const size_t rbase = ((size_t)b * PCN + (size_t)(n * 64) * 8 + cch) * KPAD + k0;
    {   // X fill: PRMT repack of bf16 pairs into paired A-layout (k0+m <= 1023 always)
        const int m = tid & 127, ih = tid >> 7;
        const uint32_t* src = g_Y + rbase + m;
        for (int j = 2 * ih; j < 64; j += 4) {
            uint32_t w0 = src[(size_t)j * jstride];
            uint32_t w1 = src[(size_t)(j + 1) * jstride];
            uint32_t rp, ip;
            asm("prmt.b32 %0, %1, %2, 0x5410;" : "=r"(rp) : "r"(w0), "r"(w1));
            asm("prmt.b32 %0, %1, %2, 0x7632;" : "=r"(ip) : "r"(w0), "r"(w1));
            Xa[m * XSTR + npw(j >> 1)]        = rp;
            Xa[m * XSTR + npw(32 + (j >> 1))] = ip;
        }
    }
    __syncthreads();

    const int r0 = wq * 32 + g;
    const int co = 2 * c;

    // ---- layer 1
    float a0c[8][4], a1c[8][4];
    #pragma unroll
    for (int t = 0; t < 8; ++t) {
        a0c[t][0] = a0c[t][1] = a0c[t][2] = a0c[t][3] = 0.f;
        a1c[t][0] = a1c[t][1] = a1c[t][2] = a1c[t][3] = 0.f;
    }
    #pragma unroll
    for (int s = 0; s < 8; ++s) {
        const int cs = 8 * s + co;
        uint2 aa0 = *(const uint2*)(Xa + r0 * XSTR + cs);
        uint2 ab0 = *(const uint2*)(Xa + (r0 + 8) * XSTR + cs);
        uint2 aa1 = *(const uint2*)(Xa + (r0 + 16) * XSTR + cs);
        uint2 ab1 = *(const uint2*)(Xa + (r0 + 24) * XSTR + cs);
        #pragma unroll
        for (int t = 0; t < 8; ++t) {
            const int nr = (wh * 8 + t) * 8 + g;
            uint2 bw = *(const uint2*)(W1s + nr * XSTR + cs);
            mma16816(a0c[t], aa0.x, ab0.x, aa0.y, ab0.y, bw.x, bw.y);
            mma16816(a1c[t], aa1.x, ab1.x, aa1.y, ab1.y, bw.x, bw.y);
        }
    }
    uint32_t h00[8], h01[8], h10[8], h11[8];
    #pragma unroll
    for (int t = 0; t < 8; ++t) {
        float2 bv = *(float2*)(bias1 + (wh * 8 + t) * 8 + co);
        h00[t] = pkbf(gelu_fast(a0c[t][0] + bv.x), gelu_fast(a0c[t][1] + bv.y));
        h01[t] = pkbf(gelu_fast(a0c[t][2] + bv.x), gelu_fast(a0c[t][3] + bv.y));
        h10[t] = pkbf(gelu_fast(a1c[t][0] + bv.x), gelu_fast(a1c[t][1] + bv.y));
        h11[t] = pkbf(gelu_fast(a1c[t][2] + bv.x), gelu_fast(a1c[t][3] + bv.y));
    }
    __syncthreads();   // all Xa reads done -> H overlay safe
    #pragma unroll
    for (int t = 0; t < 8; ++t) {
        const int np = npw(wh * 32 + t * 4 + c);
        Xa[r0 * XSTR + np]        = h00[t];
        Xa[(r0 + 8) * XSTR + np]  = h01[t];
        Xa[(r0 + 16) * XSTR + np] = h10[t];
        Xa[(r0 + 24) * XSTR + np] = h11[t];
    }
    __syncthreads();

    // ---- layer 2
    #pragma unroll
    for (int t = 0; t < 8; ++t) {
        a0c[t][0] = a0c[t][1] = a0c[t][2] = a0c[t][3] = 0.f;
        a1c[t][0] = a1c[t][1] = a1c[t][2] = a1c[t][3] = 0.f;
    }
    #pragma unroll
    for (int s = 0; s < 8; ++s) {
        const int cs = 8 * s + co;
        uint2 aa0 = *(const uint2*)(Xa + r0 * XSTR + cs);
        uint2 ab0 = *(const uint2*)(Xa + (r0 + 8) * XSTR + cs);
        uint2 aa1 = *(const uint2*)(Xa + (r0 + 16) * XSTR + cs);
        uint2 ab1 = *(const uint2*)(Xa + (r0 + 24) * XSTR + cs);
        #pragma unroll
        for (int t = 0; t < 8; ++t) {
            const int nr = (wh * 8 + t) * 8 + g;
            uint2 bw = *(const uint2*)(W2s + nr * XSTR + cs);
            mma16816(a0c[t], aa0.x, ab0.x, aa0.y, ab0.y, bw.x, bw.y);
            mma16816(a1c[t], aa1.x, ab1.x, aa1.y, ab1.y, bw.x, bw.y);
        }
    }
    __syncthreads();   // all H reads done -> O overlay safe

    {   // epilogue 2: bias + bf16 stores into Oa/Ob
        uint16_t* O = wh ? Ob : Oa;
        const float* bs = bias2 + wh * 64;
        #pragma unroll
        for (int t = 0; t < 8; ++t) {
            const int j = t * 8 + co;
            float2 bv = make_float2(bs[j], bs[j + 1]);
            __nv_bfloat16 v0 = __float2bfloat16(a0c[t][0] + bv.x);
            __nv_bfloat16 v1 = __float2bfloat16(a0c[t][1] + bv.y);
            __nv_bfloat16 v2 = __float2bfloat16(a0c[t][2] + bv.x);
            __nv_bfloat16 v3 = __float2bfloat16(a0c[t][3] + bv.y);
            __nv_bfloat16 v4 = __float2bfloat16(a1c[t][0] + bv.x);
            __nv_bfloat16 v5 = __float2bfloat16(a1c[t][1] + bv.y);
            __nv_bfloat16 v6 = __float2bfloat16(a1c[t][2] + bv.x);
            __nv_bfloat16 v7 = __float2bfloat16(a1c[t][3] + bv.y);
            O[r0 * XSTR + j]            = *(uint16_t*)&v0;
            O[r0 * XSTR + j + 1]        = *(uint16_t*)&v1;
            O[(r0 + 8) * XSTR + j]      = *(uint16_t*)&v2;
            O[(r0 + 8) * XSTR + j + 1]  = *(uint16_t*)&v3;
            O[(r0 + 16) * XSTR + j]     = *(uint16_t*)&v4;
            O[(r0 + 16) * XSTR + j + 1] = *(uint16_t*)&v5;
            O[(r0 + 24) * XSTR + j]     = *(uint16_t*)&v6;
            O[(r0 + 24) * XSTR + j + 1] = *(uint16_t*)&v7;
        }
    }
    __syncthreads();

    {   // coalesced bf16x2 store
        const int m = tid & 127, jh = tid >> 7;
        uint32_t* dst = g_Y + rbase + m;
        for (int j = jh; j < 64; j += 2)
            dst[(size_t)j * jstride] =
                (uint32_t)Oa[m * XSTR + j] | ((uint32_t)Ob[m * XSTR + j] << 16);
    }
}

// ---------- K3: inverse rfft + residual (pack fused into load) ----------
__global__ __launch_bounds__(256, 3) void k_inv(const float* __restrict__ x,
                                                float* __restrict__ out) {
    float2* sm = (float2*)smbase;
    float2* W = sm;
    float2* lines = sm + 1024;
    const int tid = threadIdx.x;
    const int u = tid >> 6, t = tid & 63;
    const int pc0 = blockIdx.x * 4;
    const int b = blockIdx.y;

    for (int j = tid; j < 1024; j += 256) W[j] = g_W1024[j];
    float2* ls = lines + u * 1026;
    {
        const uint32_t* src = g_Y + ((size_t)(b * PCN + pc0 + u)) * KPAD;
        const float SCI = 0.04419417382415922f;
        for (int k = t; k <= 512; k += 64) {
            float2 Xk = upbf(src[k]);
            float2 Xj = upbf(src[1024 - k]);
            if (k == 0) { Xk.y = 0.f; Xj.y = 0.f; }
            float ex = 0.5f * (Xk.x + Xj.x), ey = 0.5f * (Xk.y - Xj.y);
            float dx = 0.5f * (Xk.x - Xj.x), dy = 0.5f * (Xk.y + Xj.y);
            float2 wv = g_Whalf[k];
            float ox = wv.x * dx - wv.y * dy;
            float oy = wv.x * dy + wv.y * dx;
            ls[PHY(k)] = make_float2(SCI * (ex - oy), SCI * (ey + ox));
            if (k > 0 && k < 512)
                ls[PHY(1024 - k)] = make_float2(SCI * (ex + oy), SCI * (ox - ey));
        }
    }
    __syncthreads();

    fft1024_f(ls, W, t, true);

    {
        const float* s0 = (const float*)lines;
        const float* xb = x + (size_t)b * LL * PCN + pc0;
        float* ob = out + (size_t)b * LL * PCN + pc0;
        for (int l = tid; l < 2048; l += 256) {
            float4 xv = *(const float4*)(xb + (size_t)l * PCN);
            int fo = 2 * PHY(l >> 1) + (l & 1);
            float4 r;
            r.x = xv.x + s0[0 * 2052 + fo];
            r.y = xv.y + s0[1 * 2052 + fo];
            r.z = xv.z + s0[2 * 2052 + fo];
            r.w = xv.w + s0[3 * 2052 + fo];
            *(float4*)(ob + (size_t)l * PCN) = r;
        }
    }
}

extern "C" void kernel_launch(void* const* d_in, const int* in_sizes, int n_in,
                              void* d_out, int out_size) {
    const float* x  = (const float*)d_in[0];
    const float* w1 = (const float*)d_in[1];
    const float* b1 = (const float*)d_in[2];
    const float* w2 = (const float*)d_in[3];
    const float* b2 = (const float*)d_in[4];
    float* out = (float*)d_out;

    const size_t s1 = (size_t)(1024 + 4 * 1025) * sizeof(float2);   // 40,992 B
    const size_t s2 = (size_t)3 * 128 * XSTR * 4 + 1024;            // 108,544 B
    const size_t s3 = (size_t)(1024 + 4 * 1026) * sizeof(float2);   // 41,024 B

    cudaFuncSetAttribute(k_fwd, cudaFuncAttributeMaxDynamicSharedMemorySize, (int)s1);
    cudaFuncSetAttribute(k_mlp, cudaFuncAttributeMaxDynamicSharedMemorySize, (int)s2);
    cudaFuncSetAttribute(k_inv, cudaFuncAttributeMaxDynamicSharedMemorySize, (int)s3);

    k_tw<<<1, 256>>>();
    k_wprep<<<dim3(8, 2), 256>>>(w1, w2);
    k_fwd<<<dim3(PCN / 4, BB), 256, s1>>>(x);
    k_nyq<<<dim3(8, 8, BB), 128>>>(b1, b2);
    k_mlp<<<dim3(8, 64, BB), 256, s2>>>(b1, b2);
    k_inv<<<dim3(PCN / 4, BB), 256, s3>>>(x, out);
}